// round 15
// baseline (speedup 1.0000x reference)
#include <cuda_runtime.h>
#include <cuda_bf16.h>
#include <math.h>

#define NN 50000
#define NE 600000
#define ET (NE + NN)
#define HID 128
#define NH 4
#define HD 32
#define NF 15
#define EF 10
#define LAYERS 3
#define SCAN_NB 196
#define POOL_NB 256

// ---------------- scratch (static device globals; zero-initialized at load) ----------------
__device__ float g_h[(size_t)NN * HID];
__device__ float g_hp[(size_t)NN * HID];
__device__ float g_as[NN * NH];
__device__ float g_ad[NN * NH];
__device__ float4 g_ae3[(size_t)LAYERS * ET];   // a_e per layer, CSR order (self slots = row mean)
__device__ int   g_cnt[NN];          // zeroed after use in k_scan
__device__ int   g_rowptr[NN + 1];
__device__ int   g_cursor[NN];       // zeroed in k_scan (before k_fill uses it)
__device__ int   g_csr_src[ET];
__device__ int   g_selfpos[NN];      // CSR position of node i's self-loop
__device__ int   g_ticket;           // re-zeroed in k_fill
__device__ int   g_poolctr;          // re-zeroed by last pool block
__device__ volatile unsigned long long g_pub[SCAN_NB];  // re-zeroed in k_fill
__device__ float g_psum[POOL_NB * HID];
__device__ float g_pmax[POOL_NB * HID];

// packed f32x2 helpers (FFMA2: full-rate fp32 path)
__device__ __forceinline__ unsigned long long pk2(float lo, float hi) {
    unsigned long long r;
    asm("mov.b64 %0,{%1,%2};" : "=l"(r) : "f"(lo), "f"(hi));
    return r;
}
__device__ __forceinline__ void upk2(unsigned long long v, float& lo, float& hi) {
    asm("mov.b64 {%0,%1},%2;" : "=f"(lo), "=f"(hi) : "l"(v));
}
__device__ __forceinline__ void ffma2(unsigned long long& d, unsigned long long a, unsigned long long b) {
    asm("fma.rn.f32x2 %0, %1, %2, %0;" : "+l"(d) : "l"(a), "l"(b));
}

// ---------------- degree histogram ----------------
__global__ void k_hist(const int* __restrict__ ei) {
    int e = blockIdx.x * blockDim.x + threadIdx.x;
    if (e >= NE) return;
    atomicAdd(&g_cnt[ei[NE + e]], 1);
}

// ---------------- single-kernel scan of (cnt+1), ticketed + parallel lookback ----------------
__global__ void k_scan() {
    __shared__ int s[256];
    __shared__ int s2[256];
    __shared__ int sbid;
    int t = threadIdx.x;
    if (t == 0) sbid = atomicAdd(&g_ticket, 1);
    __syncthreads();
    int bid = sbid;
    int idx = bid * 256 + t;
    int val = (idx < NN) ? (g_cnt[idx] + 1) : 0;
    if (idx < NN) { g_cnt[idx] = 0; g_cursor[idx] = 0; }  // reset for next call
    s[t] = val;
    __syncthreads();
    for (int off = 1; off < 256; off <<= 1) {
        int v = (t >= off) ? s[t - off] : 0;
        __syncthreads();
        if (t >= off) s[t] += v;
        __syncthreads();
    }
    if (t == 255) g_pub[bid] = (((unsigned long long)(unsigned)s[255]) << 1) | 1ull;
    // parallel lookback: sum totals of all previous blocks
    int psum = 0;
    for (int j = t; j < bid; j += 256) {
        unsigned long long v;
        do { v = g_pub[j]; } while (!(v & 1ull));
        psum += (int)(v >> 1);
    }
    s2[t] = psum;
    __syncthreads();
    for (int off = 128; off; off >>= 1) {
        if (t < off) s2[t] += s2[t + off];
        __syncthreads();
    }
    int prev = s2[0];
    if (idx < NN) g_rowptr[idx] = prev + s[t] - val;
    if (idx == NN) g_rowptr[NN] = ET;
}

// ---------------- CSR fill fused with a_e computation for all 3 layers ----------------
__global__ void k_fill(const int* __restrict__ ei, const float* __restrict__ edge_attr,
                       const float* __restrict__ lin_edge, const float* __restrict__ att_edge) {
    __shared__ float sM[LAYERS * EF * NH];   // 120
    int t = threadIdx.x;
    if (t < LAYERS * EF * NH) {
        int l = t / (EF * NH);
        int r = t % (EF * NH);
        int f = r >> 2, hh = r & 3;
        float s = 0.0f;
#pragma unroll
        for (int d = 0; d < HD; d++)
            s += lin_edge[((size_t)l * EF + f) * HID + hh * HD + d] * att_edge[l * NH * HD + hh * HD + d];
        sM[t] = s;
    }
    __syncthreads();
    int idx = blockIdx.x * blockDim.x + t;
    if (idx < SCAN_NB) g_pub[idx] = 0ull;     // reset scan state for next call
    if (idx == SCAN_NB) g_ticket = 0;
    if (idx < NE) {
        int dst = ei[NE + idx];
        int pos = g_rowptr[dst] + atomicAdd(&g_cursor[dst], 1);
        g_csr_src[pos] = ei[idx];
        const float2* ea = (const float2*)(edge_attr + (size_t)idx * EF);
        float2 e0 = ea[0], e1 = ea[1], e2 = ea[2], e3 = ea[3], e4 = ea[4];
        float vv[EF] = {e0.x, e0.y, e1.x, e1.y, e2.x, e2.y, e3.x, e3.y, e4.x, e4.y};
#pragma unroll
        for (int l = 0; l < LAYERS; l++) {
            float o[NH];
#pragma unroll
            for (int hh = 0; hh < NH; hh++) {
                float s = 0.0f;
#pragma unroll
                for (int f = 0; f < EF; f++) s += vv[f] * sM[l * 40 + f * NH + hh];
                o[hh] = s;
            }
            g_ae3[(size_t)l * ET + pos] = make_float4(o[0], o[1], o[2], o[3]);
        }
    } else if (idx < ET) {
        int i = idx - NE;
        int pos = g_rowptr[i] + atomicAdd(&g_cursor[i], 1);
        g_csr_src[pos] = i;
        g_selfpos[i] = pos;
        float4 z = make_float4(0.f, 0.f, 0.f, 0.f);
#pragma unroll
        for (int l = 0; l < LAYERS; l++) g_ae3[(size_t)l * ET + pos] = z;
    }
}

// ---------------- self-loop a_e = mean of row's real-edge a_e (linear in ea) ----------------
__global__ void k_aeself() {
    int t = threadIdx.x, lane = t & 31, w = t >> 5;
    int n = blockIdx.x * 4 + w;
    if (n >= NN) return;
    int rs = g_rowptr[n], re = g_rowptr[n + 1];
    int selfpos = g_selfpos[n];
    float4 acc[LAYERS];
#pragma unroll
    for (int l = 0; l < LAYERS; l++) acc[l] = make_float4(0.f, 0.f, 0.f, 0.f);
    for (int p = rs + lane; p < re; p += 32) {
        // self slot was zeroed in k_fill, so unconditional sum is exact
#pragma unroll
        for (int l = 0; l < LAYERS; l++) {
            float4 v = g_ae3[(size_t)l * ET + p];
            acc[l].x += v.x; acc[l].y += v.y; acc[l].z += v.z; acc[l].w += v.w;
        }
    }
#pragma unroll
    for (int l = 0; l < LAYERS; l++) {
#pragma unroll
        for (int off = 16; off; off >>= 1) {
            acc[l].x += __shfl_xor_sync(0xffffffffu, acc[l].x, off);
            acc[l].y += __shfl_xor_sync(0xffffffffu, acc[l].y, off);
            acc[l].z += __shfl_xor_sync(0xffffffffu, acc[l].z, off);
            acc[l].w += __shfl_xor_sync(0xffffffffu, acc[l].w, off);
        }
    }
    if (lane == 0) {
        int cnt = re - rs - 1;
        float inv = 1.0f / fmaxf((float)cnt, 1.0f);
#pragma unroll
        for (int l = 0; l < LAYERS; l++) {
            float4 o = make_float4(acc[l].x * inv, acc[l].y * inv, acc[l].z * inv, acc[l].w * inv);
            g_ae3[(size_t)l * ET + selfpos] = o;
        }
    }
}

// ---------------- node encoder ----------------
__global__ void k_encoder(const float* __restrict__ x, const float* __restrict__ enc_w,
                          const float* __restrict__ enc_b) {
    __shared__ float sx[32 * NF];
    int t = threadIdx.x;
    int n0 = blockIdx.x * 32;
    for (int idx = t; idx < 32 * NF; idx += 128) {
        int r = idx / NF, f = idx % NF;
        int n = n0 + r;
        sx[idx] = (n < NN) ? x[(size_t)n * NF + f] : 0.0f;
    }
    float wreg[NF];
#pragma unroll
    for (int f = 0; f < NF; f++) wreg[f] = enc_w[f * HID + t];
    float b = enc_b[t];
    __syncthreads();
    for (int r = 0; r < 32; r++) {
        int n = n0 + r;
        if (n >= NN) break;
        float a = b;
#pragma unroll
        for (int f = 0; f < NF; f++) a += sx[r * NF + f] * wreg[f];
        g_h[(size_t)n * HID + t] = fmaxf(a, 0.0f);
    }
}

// ---------------- hp = h @ W[l], tiled with f32x2; a_s/a_d fused ----------------
__global__ void k_gemm(const float* __restrict__ gat_lin_w,
                       const float* __restrict__ att_src,
                       const float* __restrict__ att_dst, int l) {
    __shared__ float sAT[32 * 66];    // [k][row], padded
    __shared__ float sW[32 * 128];    // [k][col]
    int t = threadIdx.x;
    int tx = t & 31, ty = t >> 5;
    int n0 = blockIdx.x * 64;
    const float* W = gat_lin_w + (size_t)l * HID * HID;

    unsigned long long acc[4][4];
#pragma unroll
    for (int r = 0; r < 4; r++)
#pragma unroll
        for (int c = 0; c < 4; c++) acc[r][c] = 0ull;

    for (int kt = 0; kt < 4; kt++) {
#pragma unroll
        for (int i = 0; i < 4; i++) {
            int q = t + i * 256;
            int row = q >> 5, c4 = q & 31;
            float4 wv = *(const float4*)&W[(size_t)(kt * 32 + row) * 128 + c4 * 4];
            *(float4*)&sW[row * 128 + c4 * 4] = wv;
        }
#pragma unroll
        for (int i = 0; i < 2; i++) {
            int q = t + i * 256;
            int row = q >> 3, k4 = q & 7;
            int gr = n0 + row; if (gr >= NN) gr = NN - 1;
            float4 av = *(const float4*)&g_h[(size_t)gr * 128 + kt * 32 + k4 * 4];
            sAT[(k4 * 4 + 0) * 66 + row] = av.x;
            sAT[(k4 * 4 + 1) * 66 + row] = av.y;
            sAT[(k4 * 4 + 2) * 66 + row] = av.z;
            sAT[(k4 * 4 + 3) * 66 + row] = av.w;
        }
        __syncthreads();
#pragma unroll
        for (int k = 0; k < 32; k++) {
            float4 bv = *(const float4*)&sW[k * 128 + tx * 4];
            unsigned long long b0 = pk2(bv.x, bv.x), b1 = pk2(bv.y, bv.y);
            unsigned long long b2 = pk2(bv.z, bv.z), b3 = pk2(bv.w, bv.w);
#pragma unroll
            for (int r = 0; r < 4; r++) {
                unsigned long long a2 = *(const unsigned long long*)&sAT[k * 66 + ty * 8 + 2 * r];
                ffma2(acc[r][0], a2, b0);
                ffma2(acc[r][1], a2, b1);
                ffma2(acc[r][2], a2, b2);
                ffma2(acc[r][3], a2, b3);
            }
        }
        __syncthreads();
    }

    float attS[4], attD[4];
#pragma unroll
    for (int c = 0; c < 4; c++) {
        attS[c] = att_src[l * HID + tx * 4 + c];
        attD[c] = att_dst[l * HID + tx * 4 + c];
    }
    int head = tx >> 3;
#pragma unroll
    for (int r = 0; r < 4; r++) {
        float lo0, hi0, lo1, hi1, lo2, hi2, lo3, hi3;
        upk2(acc[r][0], lo0, hi0);
        upk2(acc[r][1], lo1, hi1);
        upk2(acc[r][2], lo2, hi2);
        upk2(acc[r][3], lo3, hi3);
        int rowA = ty * 8 + 2 * r;
        int nA = n0 + rowA, nB = nA + 1;
        float4 oA = make_float4(lo0, lo1, lo2, lo3);
        float4 oB = make_float4(hi0, hi1, hi2, hi3);
        if (nA < NN) *(float4*)&g_hp[(size_t)nA * 128 + tx * 4] = oA;
        if (nB < NN) *(float4*)&g_hp[(size_t)nB * 128 + tx * 4] = oB;
        float sA = oA.x * attS[0] + oA.y * attS[1] + oA.z * attS[2] + oA.w * attS[3];
        float dA = oA.x * attD[0] + oA.y * attD[1] + oA.z * attD[2] + oA.w * attD[3];
        float sB = oB.x * attS[0] + oB.y * attS[1] + oB.z * attS[2] + oB.w * attS[3];
        float dB = oB.x * attD[0] + oB.y * attD[1] + oB.z * attD[2] + oB.w * attD[3];
#pragma unroll
        for (int off = 4; off; off >>= 1) {
            sA += __shfl_xor_sync(0xffffffffu, sA, off);
            dA += __shfl_xor_sync(0xffffffffu, dA, off);
            sB += __shfl_xor_sync(0xffffffffu, sB, off);
            dB += __shfl_xor_sync(0xffffffffu, dB, off);
        }
        if ((tx & 7) == 0) {
            if (nA < NN) { g_as[nA * 4 + head] = sA; g_ad[nA * 4 + head] = dA; }
            if (nB < NN) { g_as[nB * 4 + head] = sB; g_ad[nB * 4 + head] = dB; }
        }
    }
}

// ---------------- warp-per-node aggregation (staged edge weights) + residual + LN ----------------
__global__ void k_agg(const float* __restrict__ gat_bias, const float* __restrict__ ln_g,
                      const float* __restrict__ ln_b, int l) {
    __shared__ float4 sw[4][32];
    __shared__ int ssrc[4][32];
    int t = threadIdx.x, lane = t & 31, w = t >> 5;
    int n = blockIdx.x * 4 + w;
    if (n >= NN) return;
    int rs = g_rowptr[n];
    int deg = g_rowptr[n + 1] - rs;
    int head = lane >> 3;
    float4 ad4 = *(const float4*)&g_ad[n * 4];
    const float* swf = (const float*)&sw[w][0];
    const float4* ae = g_ae3 + (size_t)l * ET;

    float4 acc = make_float4(0.f, 0.f, 0.f, 0.f);
    float4 dn  = make_float4(0.f, 0.f, 0.f, 0.f);
    for (int c0 = 0; c0 < deg; c0 += 32) {
        int cl = min(32, deg - c0);
        if (lane < cl) {
            int p = rs + c0 + lane;
            int src = g_csr_src[p];
            float4 as4 = *(const float4*)&g_as[src * 4];
            float4 ae4 = ae[p];
            float a0 = as4.x + ad4.x + ae4.x; a0 = fmaxf(a0, 0.2f * a0);
            float a1 = as4.y + ad4.y + ae4.y; a1 = fmaxf(a1, 0.2f * a1);
            float a2 = as4.z + ad4.z + ae4.z; a2 = fmaxf(a2, 0.2f * a2);
            float a3 = as4.w + ad4.w + ae4.w; a3 = fmaxf(a3, 0.2f * a3);
            float4 w4 = make_float4(__expf(a0), __expf(a1), __expf(a2), __expf(a3));
            sw[w][lane] = w4;
            ssrc[w][lane] = src;
            dn.x += w4.x; dn.y += w4.y; dn.z += w4.z; dn.w += w4.w;
        }
        __syncwarp();
        int j = 0;
#pragma unroll 4
        for (; j < cl; j++) {
            int sj = ssrc[w][j];
            float wj = swf[j * 4 + head];
            float4 v = *(const float4*)&g_hp[(size_t)sj * 128 + lane * 4];
            acc.x += wj * v.x;
            acc.y += wj * v.y;
            acc.z += wj * v.z;
            acc.w += wj * v.w;
        }
        __syncwarp();
    }
#pragma unroll
    for (int off = 16; off; off >>= 1) {
        dn.x += __shfl_xor_sync(0xffffffffu, dn.x, off);
        dn.y += __shfl_xor_sync(0xffffffffu, dn.y, off);
        dn.z += __shfl_xor_sync(0xffffffffu, dn.z, off);
        dn.w += __shfl_xor_sync(0xffffffffu, dn.w, off);
    }
    float den = (head == 0) ? dn.x : (head == 1) ? dn.y : (head == 2) ? dn.z : dn.w;
    float inv = 1.0f / den;

    // residual + LayerNorm (warp-local)
    float4 hv = *(const float4*)&g_h[(size_t)n * 128 + lane * 4];
    float4 b4 = *(const float4*)&gat_bias[l * 128 + lane * 4];
    float4 v;
    v.x = hv.x + acc.x * inv + b4.x;
    v.y = hv.y + acc.y * inv + b4.y;
    v.z = hv.z + acc.z * inv + b4.z;
    v.w = hv.w + acc.w * inv + b4.w;
    float s = v.x + v.y + v.z + v.w;
#pragma unroll
    for (int off = 16; off; off >>= 1) s += __shfl_xor_sync(0xffffffffu, s, off);
    float mu = s * (1.0f / 128.0f);
    float4 d;
    d.x = v.x - mu; d.y = v.y - mu; d.z = v.z - mu; d.w = v.w - mu;
    float sq = d.x * d.x + d.y * d.y + d.z * d.z + d.w * d.w;
#pragma unroll
    for (int off = 16; off; off >>= 1) sq += __shfl_xor_sync(0xffffffffu, sq, off);
    float var = sq * (1.0f / 128.0f);
    float r = rsqrtf(var + 1e-5f);
    float4 g4 = *(const float4*)&ln_g[l * 128 + lane * 4];
    float4 bb4 = *(const float4*)&ln_b[l * 128 + lane * 4];
    float4 o;
    o.x = d.x * r * g4.x + bb4.x;
    o.y = d.y * r * g4.y + bb4.y;
    o.z = d.z * r * g4.z + bb4.z;
    o.w = d.w * r * g4.w + bb4.w;
    *(float4*)&g_h[(size_t)n * 128 + lane * 4] = o;
}

// ---------------- fused pooling + global head (last-block-done) ----------------
__global__ void k_pool(const float* __restrict__ u, const float* __restrict__ pool_w,
                       const float* __restrict__ pool_b, const float* __restrict__ pool_ln_g,
                       const float* __restrict__ pool_ln_b, const float* __restrict__ glob_w1,
                       const float* __restrict__ glob_b1, const float* __restrict__ glob_w2,
                       const float* __restrict__ glob_b2, float* __restrict__ out) {
    int t = threadIdx.x, b = blockIdx.x;
    float s = 0.0f, m = -3.0e38f;
    for (int n = b; n < NN; n += POOL_NB) {
        float v = g_h[(size_t)n * HID + t];
        s += v;
        m = fmaxf(m, v);
    }
    g_psum[b * HID + t] = s;
    g_pmax[b * HID + t] = m;
    __threadfence();
    __shared__ int slast;
    if (t == 0) {
        int c = atomicAdd(&g_poolctr, 1);
        slast = (c == POOL_NB - 1);
    }
    __syncthreads();
    if (!slast) return;
    if (t == 0) g_poolctr = 0;   // reset for next call

    __shared__ float pooled[3 * HID + 8];
    __shared__ float gg[8];
    __shared__ float gv[8];
    __shared__ float z[32];
    float s2 = 0.0f, m2 = -3.0e38f;
    for (int bb = 0; bb < POOL_NB; bb++) {
        s2 += g_psum[bb * HID + t];
        m2 = fmaxf(m2, g_pmax[bb * HID + t]);
    }
    pooled[t] = s2 * (1.0f / (float)NN);
    pooled[HID + t] = m2;
    pooled[2 * HID + t] = s2;
    if (t < 8) pooled[3 * HID + t] = u[t];
    __syncthreads();
    if (t < 8) {
        float a = pool_b[t];
        for (int f = 0; f < 3 * HID + 8; f++) a += pooled[f] * pool_w[f * 8 + t];
        gg[t] = fmaxf(a, 0.0f);
    }
    __syncthreads();
    if (t == 0) {
        float mu = 0.0f;
        for (int o = 0; o < 8; o++) mu += gg[o];
        mu *= 0.125f;
        float var = 0.0f;
        for (int o = 0; o < 8; o++) { float dd = gg[o] - mu; var += dd * dd; }
        var *= 0.125f;
        float inv = rsqrtf(var + 1e-5f);
        for (int o = 0; o < 8; o++) gv[o] = (gg[o] - mu) * inv * pool_ln_g[o] + pool_ln_b[o];
    }
    __syncthreads();
    if (t < 32) {
        float a = glob_b1[t];
        for (int f = 0; f < 8; f++) a += gv[f] * glob_w1[f * 32 + t];
        z[t] = fmaxf(a, 0.0f);
    }
    __syncthreads();
    if (t < 4) {
        float y = glob_b2[t];
        for (int k = 0; k < 32; k++) y += z[k] * glob_w2[k * 4 + t];
        out[(size_t)9 * NN + t] = tanhf(y);
    }
}

// ---------------- heads: tiled f32x2 GEMM (64 rows x 160 cols) + fused stage 2 ----------------
__global__ void k_heads(const float* __restrict__ head_w1, const float* __restrict__ head_b1,
                        const float* __restrict__ head_w2, const float* __restrict__ head_b2,
                        const float* __restrict__ strat_w1, const float* __restrict__ strat_b1,
                        const float* __restrict__ strat_w2, const float* __restrict__ strat_b2,
                        float* __restrict__ out) {
    __shared__ char smraw[44 * 1024];
    float* sAT = (float*)smraw;                  // 32*66 floats
    float* sWh = (float*)(smraw + 8448);         // 32*160 floats
    float* sZ  = (float*)smraw;                  // 64*164 floats (reuses phase-1 space)
    __shared__ float sY[64 * 5];

    int t = threadIdx.x;                         // 320 threads
    int tx = t % 40, ty = t / 40;
    int n0 = blockIdx.x * 64;

    unsigned long long acc[4][4];
#pragma unroll
    for (int r = 0; r < 4; r++)
#pragma unroll
        for (int c = 0; c < 4; c++) acc[r][c] = 0ull;

    for (int kt = 0; kt < 4; kt++) {
        for (int q = t; q < 32 * 160; q += 320) {
            int k = q / 160, j = q % 160;
            float wv;
            if (j < 128) wv = head_w1[(size_t)(j >> 5) * (HID * 32) + (size_t)(kt * 32 + k) * 32 + (j & 31)];
            else         wv = strat_w1[(size_t)(kt * 32 + k) * 32 + (j - 128)];
            sWh[k * 160 + j] = wv;
        }
        for (int q = t; q < 512; q += 320) {
            int row = q >> 3, k4 = q & 7;
            int gr = n0 + row; if (gr >= NN) gr = NN - 1;
            float4 av = *(const float4*)&g_h[(size_t)gr * 128 + kt * 32 + k4 * 4];
            sAT[(k4 * 4 + 0) * 66 + row] = av.x;
            sAT[(k4 * 4 + 1) * 66 + row] = av.y;
            sAT[(k4 * 4 + 2) * 66 + row] = av.z;
            sAT[(k4 * 4 + 3) * 66 + row] = av.w;
        }
        __syncthreads();
#pragma unroll
        for (int k = 0; k < 32; k++) {
            float4 bv = *(const float4*)&sWh[k * 160 + tx * 4];
            unsigned long long b0 = pk2(bv.x, bv.x), b1 = pk2(bv.y, bv.y);
            unsigned long long b2 = pk2(bv.z, bv.z), b3 = pk2(bv.w, bv.w);
#pragma unroll
            for (int r = 0; r < 4; r++) {
                unsigned long long a2 = *(const unsigned long long*)&sAT[k * 66 + ty * 8 + 2 * r];
                ffma2(acc[r][0], a2, b0);
                ffma2(acc[r][1], a2, b1);
                ffma2(acc[r][2], a2, b2);
                ffma2(acc[r][3], a2, b3);
            }
        }
        __syncthreads();
    }

    float b1v[4];
#pragma unroll
    for (int c = 0; c < 4; c++) {
        int j = tx * 4 + c;
        b1v[c] = (j < 128) ? head_b1[j] : strat_b1[j - 128];
    }
#pragma unroll
    for (int r = 0; r < 4; r++) {
        float lo0, hi0, lo1, hi1, lo2, hi2, lo3, hi3;
        upk2(acc[r][0], lo0, hi0);
        upk2(acc[r][1], lo1, hi1);
        upk2(acc[r][2], lo2, hi2);
        upk2(acc[r][3], lo3, hi3);
        int rowA = ty * 8 + 2 * r;
        float4 oA = make_float4(fmaxf(lo0 + b1v[0], 0.f), fmaxf(lo1 + b1v[1], 0.f),
                                fmaxf(lo2 + b1v[2], 0.f), fmaxf(lo3 + b1v[3], 0.f));
        float4 oB = make_float4(fmaxf(hi0 + b1v[0], 0.f), fmaxf(hi1 + b1v[1], 0.f),
                                fmaxf(hi2 + b1v[2], 0.f), fmaxf(hi3 + b1v[3], 0.f));
        *(float4*)&sZ[rowA * 164 + tx * 4] = oA;
        *(float4*)&sZ[(rowA + 1) * 164 + tx * 4] = oB;
    }
    __syncthreads();

    if (t < 256) {
        int r = t >> 2, hd = t & 3;
        float y = head_b2[hd];
#pragma unroll
        for (int k = 0; k < 32; k++) y += sZ[r * 164 + hd * 32 + k] * head_w2[hd * 32 + k];
        int n = n0 + r;
        if (n < NN) {
            float o = (hd == 0) ? tanhf(y) : 1.0f / (1.0f + __expf(-y));
            out[(size_t)hd * NN + n] = o;
        }
    }
    {
        int r = t / 5, s = t % 5;
        float y = strat_b2[s];
#pragma unroll
        for (int k = 0; k < 32; k++) y += sZ[r * 164 + 128 + k] * strat_w2[k * 5 + s];
        sY[r * 5 + s] = y;
    }
    __syncthreads();
    {
        int r = t / 5, s = t % 5;
        float y0 = sY[r * 5 + 0], y1 = sY[r * 5 + 1], y2 = sY[r * 5 + 2],
              y3 = sY[r * 5 + 3], y4 = sY[r * 5 + 4];
        float m = fmaxf(fmaxf(fmaxf(y0, y1), fmaxf(y2, y3)), y4);
        float den = __expf(y0 - m) + __expf(y1 - m) + __expf(y2 - m) + __expf(y3 - m) + __expf(y4 - m);
        int n = n0 + r;
        if (n < NN) out[(size_t)4 * NN + (size_t)n * 5 + s] = __expf(sY[r * 5 + s] - m) / den;
    }
}

// ---------------- launcher ----------------
extern "C" void kernel_launch(void* const* d_in, const int* in_sizes, int n_in,
                              void* d_out, int out_size) {
    const float* x          = (const float*)d_in[0];
    const int*   ei         = (const int*)d_in[1];
    const float* edge_attr  = (const float*)d_in[2];
    const float* u          = (const float*)d_in[3];
    const float* enc_w      = (const float*)d_in[4];
    const float* enc_b      = (const float*)d_in[5];
    const float* gat_lin_w  = (const float*)d_in[6];
    const float* att_src    = (const float*)d_in[7];
    const float* att_dst    = (const float*)d_in[8];
    const float* lin_edge   = (const float*)d_in[9];
    const float* att_edge   = (const float*)d_in[10];
    const float* gat_bias   = (const float*)d_in[11];
    const float* ln_g       = (const float*)d_in[12];
    const float* ln_b       = (const float*)d_in[13];
    const float* pool_w     = (const float*)d_in[14];
    const float* pool_b     = (const float*)d_in[15];
    const float* pool_ln_g  = (const float*)d_in[16];
    const float* pool_ln_b  = (const float*)d_in[17];
    const float* head_w1    = (const float*)d_in[18];
    const float* head_b1    = (const float*)d_in[19];
    const float* head_w2    = (const float*)d_in[20];
    const float* head_b2    = (const float*)d_in[21];
    const float* strat_w1   = (const float*)d_in[22];
    const float* strat_b1   = (const float*)d_in[23];
    const float* strat_w2   = (const float*)d_in[24];
    const float* strat_b2   = (const float*)d_in[25];
    const float* glob_w1    = (const float*)d_in[26];
    const float* glob_b1    = (const float*)d_in[27];
    const float* glob_w2    = (const float*)d_in[28];
    const float* glob_b2    = (const float*)d_in[29];
    float* out = (float*)d_out;

    k_hist<<<(NE + 255) / 256, 256>>>(ei);
    k_scan<<<SCAN_NB, 256>>>();
    k_fill<<<(ET + 255) / 256, 256>>>(ei, edge_attr, lin_edge, att_edge);
    k_aeself<<<(NN + 3) / 4, 128>>>();
    k_encoder<<<(NN + 31) / 32, 128>>>(x, enc_w, enc_b);
    for (int l = 0; l < LAYERS; l++) {
        k_gemm<<<(NN + 63) / 64, 256>>>(gat_lin_w, att_src, att_dst, l);
        k_agg<<<(NN + 3) / 4, 128>>>(gat_bias, ln_g, ln_b, l);
    }
    k_pool<<<POOL_NB, 128>>>(u, pool_w, pool_b, pool_ln_g, pool_ln_b,
                             glob_w1, glob_b1, glob_w2, glob_b2, out);
    k_heads<<<(NN + 63) / 64, 320>>>(head_w1, head_b1, head_w2, head_b2,
                                     strat_w1, strat_b1, strat_w2, strat_b2, out);
}

// round 17
// speedup vs baseline: 1.0530x; 1.0530x over previous
#include <cuda_runtime.h>
#include <cuda_bf16.h>
#include <math.h>

#define NN 50000
#define NE 600000
#define ET (NE + NN)
#define HID 128
#define NH 4
#define HD 32
#define NF 15
#define EF 10
#define LAYERS 3
#define SCAN_NB 196
#define POOL_NB 256

// ---------------- scratch (static device globals; zero-initialized at load) ----------------
__device__ float g_h[(size_t)NN * HID];
__device__ float g_hp[(size_t)NN * HID];
__device__ float g_as[NN * NH];
__device__ float g_ad[NN * NH];
__device__ float4 g_ae3[(size_t)LAYERS * ET];   // a_e per layer, CSR order (self slots zeroed)
__device__ int   g_cnt[NN];          // zeroed after use in k_scan
__device__ int   g_rowptr[NN + 1];
__device__ int   g_cursor[NN];       // zeroed in k_scan (before k_fill uses it)
__device__ int   g_csr_src[ET];
__device__ int   g_pos[ET];          // edge e -> CSR position; self-loop of node i at NE+i
__device__ int   g_ticket;           // re-zeroed in k_fill
__device__ int   g_poolctr;          // re-zeroed by last pool block
__device__ volatile unsigned long long g_pub[SCAN_NB];  // re-zeroed in k_fill
__device__ float g_psum[POOL_NB * HID];
__device__ float g_pmax[POOL_NB * HID];

// packed f32x2 helpers (FFMA2: full-rate fp32 path)
__device__ __forceinline__ unsigned long long pk2(float lo, float hi) {
    unsigned long long r;
    asm("mov.b64 %0,{%1,%2};" : "=l"(r) : "f"(lo), "f"(hi));
    return r;
}
__device__ __forceinline__ void upk2(unsigned long long v, float& lo, float& hi) {
    asm("mov.b64 {%0,%1},%2;" : "=f"(lo), "=f"(hi) : "l"(v));
}
__device__ __forceinline__ void ffma2(unsigned long long& d, unsigned long long a, unsigned long long b) {
    asm("fma.rn.f32x2 %0, %1, %2, %0;" : "+l"(d) : "l"(a), "l"(b));
}

// ---------------- degree histogram ----------------
__global__ void k_hist(const int* __restrict__ ei) {
    int e = blockIdx.x * blockDim.x + threadIdx.x;
    if (e >= NE) return;
    atomicAdd(&g_cnt[ei[NE + e]], 1);
}

// ---------------- single-kernel scan of (cnt+1), ticketed + parallel lookback ----------------
__global__ void k_scan() {
    __shared__ int s[256];
    __shared__ int s2[256];
    __shared__ int sbid;
    int t = threadIdx.x;
    if (t == 0) sbid = atomicAdd(&g_ticket, 1);
    __syncthreads();
    int bid = sbid;
    int idx = bid * 256 + t;
    int val = (idx < NN) ? (g_cnt[idx] + 1) : 0;
    if (idx < NN) { g_cnt[idx] = 0; g_cursor[idx] = 0; }  // reset for next call
    s[t] = val;
    __syncthreads();
    for (int off = 1; off < 256; off <<= 1) {
        int v = (t >= off) ? s[t - off] : 0;
        __syncthreads();
        if (t >= off) s[t] += v;
        __syncthreads();
    }
    if (t == 255) g_pub[bid] = (((unsigned long long)(unsigned)s[255]) << 1) | 1ull;
    // parallel lookback: sum totals of all previous blocks
    int psum = 0;
    for (int j = t; j < bid; j += 256) {
        unsigned long long v;
        do { v = g_pub[j]; } while (!(v & 1ull));
        psum += (int)(v >> 1);
    }
    s2[t] = psum;
    __syncthreads();
    for (int off = 128; off; off >>= 1) {
        if (t < off) s2[t] += s2[t + off];
        __syncthreads();
    }
    int prev = s2[0];
    if (idx < NN) g_rowptr[idx] = prev + s[t] - val;
    if (idx == NN) g_rowptr[NN] = ET;
}

// ---------------- CSR fill; stores src + pos; zeros ae3 self slots ----------------
__global__ void k_fill(const int* __restrict__ ei) {
    int idx = blockIdx.x * blockDim.x + threadIdx.x;
    if (idx < SCAN_NB) g_pub[idx] = 0ull;     // reset scan state for next call
    if (idx == SCAN_NB) g_ticket = 0;
    if (idx < NE) {
        int dst = ei[NE + idx];
        int pos = g_rowptr[dst] + atomicAdd(&g_cursor[dst], 1);
        g_csr_src[pos] = ei[idx];
        g_pos[idx] = pos;
    } else if (idx < ET) {
        int i = idx - NE;
        int pos = g_rowptr[i] + atomicAdd(&g_cursor[i], 1);
        g_csr_src[pos] = i;
        g_pos[NE + i] = pos;
        float4 z = make_float4(0.f, 0.f, 0.f, 0.f);
#pragma unroll
        for (int l = 0; l < LAYERS; l++) g_ae3[(size_t)l * ET + pos] = z;
    }
}

// ---------------- a_e for all layers: coalesced edge_attr read, scatter to CSR slots (2-edge ILP) ----------------
__global__ void k_ae3(const float* __restrict__ edge_attr, const float* __restrict__ lin_edge,
                      const float* __restrict__ att_edge) {
    __shared__ float sM[LAYERS * EF * NH];   // 120
    int t = threadIdx.x;
    if (t < LAYERS * EF * NH) {
        int l = t / (EF * NH);
        int r = t % (EF * NH);
        int f = r >> 2, hh = r & 3;
        float s = 0.0f;
#pragma unroll
        for (int d = 0; d < HD; d++)
            s += lin_edge[((size_t)l * EF + f) * HID + hh * HD + d] * att_edge[l * NH * HD + hh * HD + d];
        sM[t] = s;
    }
    __syncthreads();
    int base = blockIdx.x * 512 + t;
#pragma unroll
    for (int i = 0; i < 2; i++) {
        int e = base + i * 256;
        if (e >= NE) continue;
        const float2* ea = (const float2*)(edge_attr + (size_t)e * EF);
        float2 e0 = ea[0], e1 = ea[1], e2 = ea[2], e3 = ea[3], e4 = ea[4];
        float vv[EF] = {e0.x, e0.y, e1.x, e1.y, e2.x, e2.y, e3.x, e3.y, e4.x, e4.y};
        int pos = g_pos[e];
#pragma unroll
        for (int l = 0; l < LAYERS; l++) {
            float o[NH];
#pragma unroll
            for (int hh = 0; hh < NH; hh++) {
                float s = 0.0f;
#pragma unroll
                for (int f = 0; f < EF; f++) s += vv[f] * sM[l * 40 + f * NH + hh];
                o[hh] = s;
            }
            g_ae3[(size_t)l * ET + pos] = make_float4(o[0], o[1], o[2], o[3]);
        }
    }
}

// ---------------- node encoder ----------------
__global__ void k_encoder(const float* __restrict__ x, const float* __restrict__ enc_w,
                          const float* __restrict__ enc_b) {
    __shared__ float sx[32 * NF];
    int t = threadIdx.x;
    int n0 = blockIdx.x * 32;
    for (int idx = t; idx < 32 * NF; idx += 128) {
        int r = idx / NF, f = idx % NF;
        int n = n0 + r;
        sx[idx] = (n < NN) ? x[(size_t)n * NF + f] : 0.0f;
    }
    float wreg[NF];
#pragma unroll
    for (int f = 0; f < NF; f++) wreg[f] = enc_w[f * HID + t];
    float b = enc_b[t];
    __syncthreads();
    for (int r = 0; r < 32; r++) {
        int n = n0 + r;
        if (n >= NN) break;
        float a = b;
#pragma unroll
        for (int f = 0; f < NF; f++) a += sx[r * NF + f] * wreg[f];
        g_h[(size_t)n * HID + t] = fmaxf(a, 0.0f);
    }
}

// ---------------- hp = h @ W[l], tiled with f32x2; a_s/a_d fused ----------------
__global__ void k_gemm(const float* __restrict__ gat_lin_w,
                       const float* __restrict__ att_src,
                       const float* __restrict__ att_dst, int l) {
    __shared__ float sAT[32 * 66];    // [k][row], padded
    __shared__ float sW[32 * 128];    // [k][col]
    int t = threadIdx.x;
    int tx = t & 31, ty = t >> 5;
    int n0 = blockIdx.x * 64;
    const float* W = gat_lin_w + (size_t)l * HID * HID;

    unsigned long long acc[4][4];
#pragma unroll
    for (int r = 0; r < 4; r++)
#pragma unroll
        for (int c = 0; c < 4; c++) acc[r][c] = 0ull;

    for (int kt = 0; kt < 4; kt++) {
#pragma unroll
        for (int i = 0; i < 4; i++) {
            int q = t + i * 256;
            int row = q >> 5, c4 = q & 31;
            float4 wv = *(const float4*)&W[(size_t)(kt * 32 + row) * 128 + c4 * 4];
            *(float4*)&sW[row * 128 + c4 * 4] = wv;
        }
#pragma unroll
        for (int i = 0; i < 2; i++) {
            int q = t + i * 256;
            int row = q >> 3, k4 = q & 7;
            int gr = n0 + row; if (gr >= NN) gr = NN - 1;
            float4 av = *(const float4*)&g_h[(size_t)gr * 128 + kt * 32 + k4 * 4];
            sAT[(k4 * 4 + 0) * 66 + row] = av.x;
            sAT[(k4 * 4 + 1) * 66 + row] = av.y;
            sAT[(k4 * 4 + 2) * 66 + row] = av.z;
            sAT[(k4 * 4 + 3) * 66 + row] = av.w;
        }
        __syncthreads();
#pragma unroll
        for (int k = 0; k < 32; k++) {
            float4 bv = *(const float4*)&sW[k * 128 + tx * 4];
            unsigned long long b0 = pk2(bv.x, bv.x), b1 = pk2(bv.y, bv.y);
            unsigned long long b2 = pk2(bv.z, bv.z), b3 = pk2(bv.w, bv.w);
#pragma unroll
            for (int r = 0; r < 4; r++) {
                unsigned long long a2 = *(const unsigned long long*)&sAT[k * 66 + ty * 8 + 2 * r];
                ffma2(acc[r][0], a2, b0);
                ffma2(acc[r][1], a2, b1);
                ffma2(acc[r][2], a2, b2);
                ffma2(acc[r][3], a2, b3);
            }
        }
        __syncthreads();
    }

    float attS[4], attD[4];
#pragma unroll
    for (int c = 0; c < 4; c++) {
        attS[c] = att_src[l * HID + tx * 4 + c];
        attD[c] = att_dst[l * HID + tx * 4 + c];
    }
    int head = tx >> 3;
#pragma unroll
    for (int r = 0; r < 4; r++) {
        float lo0, hi0, lo1, hi1, lo2, hi2, lo3, hi3;
        upk2(acc[r][0], lo0, hi0);
        upk2(acc[r][1], lo1, hi1);
        upk2(acc[r][2], lo2, hi2);
        upk2(acc[r][3], lo3, hi3);
        int rowA = ty * 8 + 2 * r;
        int nA = n0 + rowA, nB = nA + 1;
        float4 oA = make_float4(lo0, lo1, lo2, lo3);
        float4 oB = make_float4(hi0, hi1, hi2, hi3);
        if (nA < NN) *(float4*)&g_hp[(size_t)nA * 128 + tx * 4] = oA;
        if (nB < NN) *(float4*)&g_hp[(size_t)nB * 128 + tx * 4] = oB;
        float sA = oA.x * attS[0] + oA.y * attS[1] + oA.z * attS[2] + oA.w * attS[3];
        float dA = oA.x * attD[0] + oA.y * attD[1] + oA.z * attD[2] + oA.w * attD[3];
        float sB = oB.x * attS[0] + oB.y * attS[1] + oB.z * attS[2] + oB.w * attS[3];
        float dB = oB.x * attD[0] + oB.y * attD[1] + oB.z * attD[2] + oB.w * attD[3];
#pragma unroll
        for (int off = 4; off; off >>= 1) {
            sA += __shfl_xor_sync(0xffffffffu, sA, off);
            dA += __shfl_xor_sync(0xffffffffu, dA, off);
            sB += __shfl_xor_sync(0xffffffffu, sB, off);
            dB += __shfl_xor_sync(0xffffffffu, dB, off);
        }
        if ((tx & 7) == 0) {
            if (nA < NN) { g_as[nA * 4 + head] = sA; g_ad[nA * 4 + head] = dA; }
            if (nB < NN) { g_as[nB * 4 + head] = sB; g_ad[nB * 4 + head] = dB; }
        }
    }
}

// ---------------- warp-per-node aggregation + inline self-loop + residual + LN ----------------
__global__ void k_agg(const float* __restrict__ gat_bias, const float* __restrict__ ln_g,
                      const float* __restrict__ ln_b, int l) {
    __shared__ float4 sw[4][32];
    __shared__ int ssrc[4][32];
    int t = threadIdx.x, lane = t & 31, w = t >> 5;
    int n = blockIdx.x * 4 + w;
    if (n >= NN) return;
    int rs = g_rowptr[n];
    int deg = g_rowptr[n + 1] - rs;
    int head = lane >> 3;
    float4 ad4 = *(const float4*)&g_ad[n * 4];
    float4 asn4 = *(const float4*)&g_as[n * 4];
    int selfpos = g_pos[NE + n];
    const float* swf = (const float*)&sw[w][0];
    const float4* ae = g_ae3 + (size_t)l * ET;

    float4 acc = make_float4(0.f, 0.f, 0.f, 0.f);
    float4 dn  = make_float4(0.f, 0.f, 0.f, 0.f);
    float4 aes = make_float4(0.f, 0.f, 0.f, 0.f);
    for (int c0 = 0; c0 < deg; c0 += 32) {
        int cl = min(32, deg - c0);
        if (lane < cl) {
            int p = rs + c0 + lane;
            int src = g_csr_src[p];
            float4 as4 = *(const float4*)&g_as[src * 4];
            float4 ae4 = ae[p];
            // self slot ae4 is zero (k_fill), so unconditional sum is exact
            aes.x += ae4.x; aes.y += ae4.y; aes.z += ae4.z; aes.w += ae4.w;
            float a0 = as4.x + ad4.x + ae4.x; a0 = fmaxf(a0, 0.2f * a0);
            float a1 = as4.y + ad4.y + ae4.y; a1 = fmaxf(a1, 0.2f * a1);
            float a2 = as4.z + ad4.z + ae4.z; a2 = fmaxf(a2, 0.2f * a2);
            float a3 = as4.w + ad4.w + ae4.w; a3 = fmaxf(a3, 0.2f * a3);
            float4 w4 = make_float4(__expf(a0), __expf(a1), __expf(a2), __expf(a3));
            if (p == selfpos) w4 = make_float4(0.f, 0.f, 0.f, 0.f);  // handled after loop
            sw[w][lane] = w4;
            ssrc[w][lane] = src;
            dn.x += w4.x; dn.y += w4.y; dn.z += w4.z; dn.w += w4.w;
        }
        __syncwarp();
        int j = 0;
#pragma unroll 4
        for (; j < cl; j++) {
            int sj = ssrc[w][j];
            float wj = swf[j * 4 + head];
            float4 v = *(const float4*)&g_hp[(size_t)sj * 128 + lane * 4];
            acc.x += wj * v.x;
            acc.y += wj * v.y;
            acc.z += wj * v.z;
            acc.w += wj * v.w;
        }
        __syncwarp();
    }
#pragma unroll
    for (int off = 16; off; off >>= 1) {
        dn.x += __shfl_xor_sync(0xffffffffu, dn.x, off);
        dn.y += __shfl_xor_sync(0xffffffffu, dn.y, off);
        dn.z += __shfl_xor_sync(0xffffffffu, dn.z, off);
        dn.w += __shfl_xor_sync(0xffffffffu, dn.w, off);
        aes.x += __shfl_xor_sync(0xffffffffu, aes.x, off);
        aes.y += __shfl_xor_sync(0xffffffffu, aes.y, off);
        aes.z += __shfl_xor_sync(0xffffffffu, aes.z, off);
        aes.w += __shfl_xor_sync(0xffffffffu, aes.w, off);
    }
    // self-loop: ae_self = mean of row's real-edge a_e (linear in ea); its hp row is hp[n]
    float invc = 1.0f / fmaxf((float)(deg - 1), 1.0f);
    float aesH = (head == 0) ? aes.x : (head == 1) ? aes.y : (head == 2) ? aes.z : aes.w;
    float asH  = (head == 0) ? asn4.x : (head == 1) ? asn4.y : (head == 2) ? asn4.z : asn4.w;
    float adH  = (head == 0) ? ad4.x : (head == 1) ? ad4.y : (head == 2) ? ad4.z : ad4.w;
    float aSelf = asH + adH + aesH * invc;
    aSelf = fmaxf(aSelf, 0.2f * aSelf);
    float wSelf = __expf(aSelf);
    float dnH = (head == 0) ? dn.x : (head == 1) ? dn.y : (head == 2) ? dn.z : dn.w;
    float den = dnH + wSelf;
    float4 hpn = *(const float4*)&g_hp[(size_t)n * 128 + lane * 4];
    acc.x += wSelf * hpn.x;
    acc.y += wSelf * hpn.y;
    acc.z += wSelf * hpn.z;
    acc.w += wSelf * hpn.w;
    float inv = 1.0f / den;

    // residual + LayerNorm (warp-local)
    float4 hv = *(const float4*)&g_h[(size_t)n * 128 + lane * 4];
    float4 b4 = *(const float4*)&gat_bias[l * 128 + lane * 4];
    float4 v;
    v.x = hv.x + acc.x * inv + b4.x;
    v.y = hv.y + acc.y * inv + b4.y;
    v.z = hv.z + acc.z * inv + b4.z;
    v.w = hv.w + acc.w * inv + b4.w;
    float s = v.x + v.y + v.z + v.w;
#pragma unroll
    for (int off = 16; off; off >>= 1) s += __shfl_xor_sync(0xffffffffu, s, off);
    float mu = s * (1.0f / 128.0f);
    float4 d;
    d.x = v.x - mu; d.y = v.y - mu; d.z = v.z - mu; d.w = v.w - mu;
    float sq = d.x * d.x + d.y * d.y + d.z * d.z + d.w * d.w;
#pragma unroll
    for (int off = 16; off; off >>= 1) sq += __shfl_xor_sync(0xffffffffu, sq, off);
    float var = sq * (1.0f / 128.0f);
    float r = rsqrtf(var + 1e-5f);
    float4 g4 = *(const float4*)&ln_g[l * 128 + lane * 4];
    float4 bb4 = *(const float4*)&ln_b[l * 128 + lane * 4];
    float4 o;
    o.x = d.x * r * g4.x + bb4.x;
    o.y = d.y * r * g4.y + bb4.y;
    o.z = d.z * r * g4.z + bb4.z;
    o.w = d.w * r * g4.w + bb4.w;
    *(float4*)&g_h[(size_t)n * 128 + lane * 4] = o;
}

// ---------------- fused pooling + global head (last-block-done) ----------------
__global__ void k_pool(const float* __restrict__ u, const float* __restrict__ pool_w,
                       const float* __restrict__ pool_b, const float* __restrict__ pool_ln_g,
                       const float* __restrict__ pool_ln_b, const float* __restrict__ glob_w1,
                       const float* __restrict__ glob_b1, const float* __restrict__ glob_w2,
                       const float* __restrict__ glob_b2, float* __restrict__ out) {
    int t = threadIdx.x, b = blockIdx.x;
    float s = 0.0f, m = -3.0e38f;
    for (int n = b; n < NN; n += POOL_NB) {
        float v = g_h[(size_t)n * HID + t];
        s += v;
        m = fmaxf(m, v);
    }
    g_psum[b * HID + t] = s;
    g_pmax[b * HID + t] = m;
    __threadfence();
    __shared__ int slast;
    if (t == 0) {
        int c = atomicAdd(&g_poolctr, 1);
        slast = (c == POOL_NB - 1);
    }
    __syncthreads();
    if (!slast) return;
    if (t == 0) g_poolctr = 0;   // reset for next call

    __shared__ float pooled[3 * HID + 8];
    __shared__ float gg[8];
    __shared__ float gv[8];
    __shared__ float z[32];
    float s2 = 0.0f, m2 = -3.0e38f;
    for (int bb = 0; bb < POOL_NB; bb++) {
        s2 += g_psum[bb * HID + t];
        m2 = fmaxf(m2, g_pmax[bb * HID + t]);
    }
    pooled[t] = s2 * (1.0f / (float)NN);
    pooled[HID + t] = m2;
    pooled[2 * HID + t] = s2;
    if (t < 8) pooled[3 * HID + t] = u[t];
    __syncthreads();
    if (t < 8) {
        float a = pool_b[t];
        for (int f = 0; f < 3 * HID + 8; f++) a += pooled[f] * pool_w[f * 8 + t];
        gg[t] = fmaxf(a, 0.0f);
    }
    __syncthreads();
    if (t == 0) {
        float mu = 0.0f;
        for (int o = 0; o < 8; o++) mu += gg[o];
        mu *= 0.125f;
        float var = 0.0f;
        for (int o = 0; o < 8; o++) { float dd = gg[o] - mu; var += dd * dd; }
        var *= 0.125f;
        float inv = rsqrtf(var + 1e-5f);
        for (int o = 0; o < 8; o++) gv[o] = (gg[o] - mu) * inv * pool_ln_g[o] + pool_ln_b[o];
    }
    __syncthreads();
    if (t < 32) {
        float a = glob_b1[t];
        for (int f = 0; f < 8; f++) a += gv[f] * glob_w1[f * 32 + t];
        z[t] = fmaxf(a, 0.0f);
    }
    __syncthreads();
    if (t < 4) {
        float y = glob_b2[t];
        for (int k = 0; k < 32; k++) y += z[k] * glob_w2[k * 4 + t];
        out[(size_t)9 * NN + t] = tanhf(y);
    }
}

// ---------------- heads: tiled f32x2 GEMM (64 rows x 160 cols) + fused stage 2 ----------------
__global__ void k_heads(const float* __restrict__ head_w1, const float* __restrict__ head_b1,
                        const float* __restrict__ head_w2, const float* __restrict__ head_b2,
                        const float* __restrict__ strat_w1, const float* __restrict__ strat_b1,
                        const float* __restrict__ strat_w2, const float* __restrict__ strat_b2,
                        float* __restrict__ out) {
    __shared__ char smraw[44 * 1024];
    float* sAT = (float*)smraw;                  // 32*66 floats
    float* sWh = (float*)(smraw + 8448);         // 32*160 floats
    float* sZ  = (float*)smraw;                  // 64*164 floats (reuses phase-1 space)
    __shared__ float sY[64 * 5];

    int t = threadIdx.x;                         // 320 threads
    int tx = t % 40, ty = t / 40;
    int n0 = blockIdx.x * 64;

    unsigned long long acc[4][4];
#pragma unroll
    for (int r = 0; r < 4; r++)
#pragma unroll
        for (int c = 0; c < 4; c++) acc[r][c] = 0ull;

    for (int kt = 0; kt < 4; kt++) {
        for (int q = t; q < 32 * 160; q += 320) {
            int k = q / 160, j = q % 160;
            float wv;
            if (j < 128) wv = head_w1[(size_t)(j >> 5) * (HID * 32) + (size_t)(kt * 32 + k) * 32 + (j & 31)];
            else         wv = strat_w1[(size_t)(kt * 32 + k) * 32 + (j - 128)];
            sWh[k * 160 + j] = wv;
        }
        for (int q = t; q < 512; q += 320) {
            int row = q >> 3, k4 = q & 7;
            int gr = n0 + row; if (gr >= NN) gr = NN - 1;
            float4 av = *(const float4*)&g_h[(size_t)gr * 128 + kt * 32 + k4 * 4];
            sAT[(k4 * 4 + 0) * 66 + row] = av.x;
            sAT[(k4 * 4 + 1) * 66 + row] = av.y;
            sAT[(k4 * 4 + 2) * 66 + row] = av.z;
            sAT[(k4 * 4 + 3) * 66 + row] = av.w;
        }
        __syncthreads();
#pragma unroll
        for (int k = 0; k < 32; k++) {
            float4 bv = *(const float4*)&sWh[k * 160 + tx * 4];
            unsigned long long b0 = pk2(bv.x, bv.x), b1 = pk2(bv.y, bv.y);
            unsigned long long b2 = pk2(bv.z, bv.z), b3 = pk2(bv.w, bv.w);
#pragma unroll
            for (int r = 0; r < 4; r++) {
                unsigned long long a2 = *(const unsigned long long*)&sAT[k * 66 + ty * 8 + 2 * r];
                ffma2(acc[r][0], a2, b0);
                ffma2(acc[r][1], a2, b1);
                ffma2(acc[r][2], a2, b2);
                ffma2(acc[r][3], a2, b3);
            }
        }
        __syncthreads();
    }

    float b1v[4];
#pragma unroll
    for (int c = 0; c < 4; c++) {
        int j = tx * 4 + c;
        b1v[c] = (j < 128) ? head_b1[j] : strat_b1[j - 128];
    }
#pragma unroll
    for (int r = 0; r < 4; r++) {
        float lo0, hi0, lo1, hi1, lo2, hi2, lo3, hi3;
        upk2(acc[r][0], lo0, hi0);
        upk2(acc[r][1], lo1, hi1);
        upk2(acc[r][2], lo2, hi2);
        upk2(acc[r][3], lo3, hi3);
        int rowA = ty * 8 + 2 * r;
        float4 oA = make_float4(fmaxf(lo0 + b1v[0], 0.f), fmaxf(lo1 + b1v[1], 0.f),
                                fmaxf(lo2 + b1v[2], 0.f), fmaxf(lo3 + b1v[3], 0.f));
        float4 oB = make_float4(fmaxf(hi0 + b1v[0], 0.f), fmaxf(hi1 + b1v[1], 0.f),
                                fmaxf(hi2 + b1v[2], 0.f), fmaxf(hi3 + b1v[3], 0.f));
        *(float4*)&sZ[rowA * 164 + tx * 4] = oA;
        *(float4*)&sZ[(rowA + 1) * 164 + tx * 4] = oB;
    }
    __syncthreads();

    if (t < 256) {
        int r = t >> 2, hd = t & 3;
        float y = head_b2[hd];
#pragma unroll
        for (int k = 0; k < 32; k++) y += sZ[r * 164 + hd * 32 + k] * head_w2[hd * 32 + k];
        int n = n0 + r;
        if (n < NN) {
            float o = (hd == 0) ? tanhf(y) : 1.0f / (1.0f + __expf(-y));
            out[(size_t)hd * NN + n] = o;
        }
    }
    {
        int r = t / 5, s = t % 5;
        float y = strat_b2[s];
#pragma unroll
        for (int k = 0; k < 32; k++) y += sZ[r * 164 + 128 + k] * strat_w2[k * 5 + s];
        sY[r * 5 + s] = y;
    }
    __syncthreads();
    {
        int r = t / 5, s = t % 5;
        float y0 = sY[r * 5 + 0], y1 = sY[r * 5 + 1], y2 = sY[r * 5 + 2],
              y3 = sY[r * 5 + 3], y4 = sY[r * 5 + 4];
        float m = fmaxf(fmaxf(fmaxf(y0, y1), fmaxf(y2, y3)), y4);
        float den = __expf(y0 - m) + __expf(y1 - m) + __expf(y2 - m) + __expf(y3 - m) + __expf(y4 - m);
        int n = n0 + r;
        if (n < NN) out[(size_t)4 * NN + (size_t)n * 5 + s] = __expf(sY[r * 5 + s] - m) / den;
    }
}

// ---------------- launcher ----------------
extern "C" void kernel_launch(void* const* d_in, const int* in_sizes, int n_in,
                              void* d_out, int out_size) {
    const float* x          = (const float*)d_in[0];
    const int*   ei         = (const int*)d_in[1];
    const float* edge_attr  = (const float*)d_in[2];
    const float* u          = (const float*)d_in[3];
    const float* enc_w      = (const float*)d_in[4];
    const float* enc_b      = (const float*)d_in[5];
    const float* gat_lin_w  = (const float*)d_in[6];
    const float* att_src    = (const float*)d_in[7];
    const float* att_dst    = (const float*)d_in[8];
    const float* lin_edge   = (const float*)d_in[9];
    const float* att_edge   = (const float*)d_in[10];
    const float* gat_bias   = (const float*)d_in[11];
    const float* ln_g       = (const float*)d_in[12];
    const float* ln_b       = (const float*)d_in[13];
    const float* pool_w     = (const float*)d_in[14];
    const float* pool_b     = (const float*)d_in[15];
    const float* pool_ln_g  = (const float*)d_in[16];
    const float* pool_ln_b  = (const float*)d_in[17];
    const float* head_w1    = (const float*)d_in[18];
    const float* head_b1    = (const float*)d_in[19];
    const float* head_w2    = (const float*)d_in[20];
    const float* head_b2    = (const float*)d_in[21];
    const float* strat_w1   = (const float*)d_in[22];
    const float* strat_b1   = (const float*)d_in[23];
    const float* strat_w2   = (const float*)d_in[24];
    const float* strat_b2   = (const float*)d_in[25];
    const float* glob_w1    = (const float*)d_in[26];
    const float* glob_b1    = (const float*)d_in[27];
    const float* glob_w2    = (const float*)d_in[28];
    const float* glob_b2    = (const float*)d_in[29];
    float* out = (float*)d_out;

    k_hist<<<(NE + 255) / 256, 256>>>(ei);
    k_scan<<<SCAN_NB, 256>>>();
    k_fill<<<(ET + 255) / 256, 256>>>(ei);
    k_ae3<<<(NE + 511) / 512, 256>>>(edge_attr, lin_edge, att_edge);
    k_encoder<<<(NN + 31) / 32, 128>>>(x, enc_w, enc_b);
    for (int l = 0; l < LAYERS; l++) {
        k_gemm<<<(NN + 63) / 64, 256>>>(gat_lin_w, att_src, att_dst, l);
        k_agg<<<(NN + 3) / 4, 128>>>(gat_bias, ln_g, ln_b, l);
    }
    k_pool<<<POOL_NB, 128>>>(u, pool_w, pool_b, pool_ln_g, pool_ln_b,
                             glob_w1, glob_b1, glob_w2, glob_b2, out);
    k_heads<<<(NN + 63) / 64, 320>>>(head_w1, head_b1, head_w2, head_b2,
                                     strat_w1, strat_b1, strat_w2, strat_b2, out);
}